// round 15
// baseline (speedup 1.0000x reference)
#include <cuda_runtime.h>
#include <mma.h>
using namespace nvcuda;

#define BATCH   8
#define NP1     1024
#define DP1     128
#define NLAYER  4
#define NHEAD   8
#define NTOK    1023
#define DSMALL  127

#define LD128   132     // padded ld for 128-col tf32 smem operand
#define LD32    36      // padded ld for 32-col smem operand

// gram: Zs[64][132] + Cs[128][132]
#define GRAM_SMEM ((64 * LD128 + DP1 * LD128) * 4)              // 101376
// final: Zs[128][132] + Es[128][132]
#define FIN_SMEM  ((2 * DP1 * LD128) * 4)                       // 135168

// ---------------------------------------------------------------------------
// g_PB[l][h][a][b] = Pfull[b][a]   (P^T, padded, PRE-ROUNDED tf32)
// g_QT[l][h][k][i] = Qfull[i][k]   (Q^T, padded, PRE-ROUNDED tf32)
// g_G[gp][b] : Gram ping-pong (layer l reads gp=l&1; update writes gp^1)
// g_R[p][b]  : R ping-pong (R[p^1] zeroed by update; R[0] by padinit)
// g_W[p][b]  : W = M^T ping-pong (I included, fp32 base)
// NOTE: tr/update wmma fragments load G/R/W DIRECTLY from global fp32;
// the tf32 MMA truncates the mantissa (vs RN) — acceptable error budget.
// ---------------------------------------------------------------------------
__device__ __align__(16) float g_PB[NLAYER][NHEAD][DP1][DP1];
__device__ __align__(16) float g_QT[NLAYER][NHEAD][DP1][DP1];
__device__ __align__(16) float g_G [2][BATCH][DP1][DP1];
__device__ __align__(16) float g_R [2][BATCH][DP1][DP1];
__device__ __align__(16) float g_W [2][BATCH][DP1][DP1];

__device__ __forceinline__ float4 tf32x4(float4 v) {
    v.x = wmma::__float_to_tf32(v.x);  v.y = wmma::__float_to_tf32(v.y);
    v.z = wmma::__float_to_tf32(v.z);  v.w = wmma::__float_to_tf32(v.w);
    return v;
}

__device__ __forceinline__ void red_add_v4(float* ptr, float4 v) {
    asm volatile("red.global.add.v4.f32 [%0], {%1, %2, %3, %4};"
                 :: "l"(ptr), "f"(v.x), "f"(v.y), "f"(v.z), "f"(v.w)
                 : "memory");
}

__device__ __forceinline__ void gds() {
#if __CUDA_ARCH__ >= 900
    cudaGridDependencySynchronize();
#endif
}

// ---------------------------------------------------------------------------
__global__ void padinit_kernel(const float* __restrict__ allparam) {
    int idx = blockIdx.x * blockDim.x + threadIdx.x;   // < 524288
    {
        int bb = idx & 127;
        int a  = (idx >> 7) & 127;
        int h  = (idx >> 14) & 7;
        int l  = idx >> 17;
        float pv = 0.0f, qv = 0.0f;
        if (bb < DSMALL && a < DSMALL) {
            const float* base = allparam
                + ((((size_t)l * NHEAD + h) * 2 + 0) * DSMALL + bb) * DSMALL + a;
            pv = base[0];
            qv = base[DSMALL * DSMALL];
        }
        if (bb == DSMALL && a == DSMALL) pv = 1.0f;
        g_PB[l][h][a][bb] = wmma::__float_to_tf32(pv);
        g_QT[l][h][a][bb] = wmma::__float_to_tf32(qv);
    }
    if (idx < BATCH * DP1 * DP1) {
        int j = idx & 127, i = (idx >> 7) & 127, b = idx >> 14;
        g_G[0][b][i][j] = 0.0f;
        g_R[0][b][i][j] = 0.0f;
        g_W[0][b][i][j] = (i == j) ? 1.0f : 0.0f;
    }
}

// ---------------------------------------------------------------------------
// Gram (tf32 wmma): G[0][b] += Zslab^T Zslab. grid (8,16), 512 thr.
// gds() guards only the reductions into the padinit-zeroed G.
// ---------------------------------------------------------------------------
__global__ __launch_bounds__(512)
void gram_kernel(const float* __restrict__ Z) {
    extern __shared__ __align__(16) float dsm[];
    float* Zs = dsm;                 // [64][132]
    float* Cs = dsm + 64 * LD128;    // [128][132]

    const int b = blockIdx.x, s = blockIdx.y;
    const int tid = threadIdx.x;
    const int w = tid >> 5;
    const int rw = (w & 7) * 16;
    const int jt = (w >> 3) * 64;

    const float* Zb = Z + (size_t)b * NP1 * DP1;
    const int m0 = s * 64;

#pragma unroll
    for (int q = 0; q < 4; q++) {
        int f = tid + q * 512;
        int row = f >> 5, c4 = (f & 31) * 4;
        float4 v = make_float4(0.f, 0.f, 0.f, 0.f);
        if (m0 + row < NTOK)
            v = tf32x4(*(const float4*)&Zb[(size_t)(m0 + row) * DP1 + c4]);
        *(float4*)&Zs[row * LD128 + c4] = v;
    }
    __syncthreads();

    wmma::fragment<wmma::accumulator, 16, 16, 8, float> c[4];
#pragma unroll
    for (int j = 0; j < 4; j++) wmma::fill_fragment(c[j], 0.0f);

#pragma unroll
    for (int k0 = 0; k0 < 64; k0 += 8) {
        wmma::fragment<wmma::matrix_a, 16, 16, 8, wmma::precision::tf32,
                       wmma::col_major> a;
        wmma::load_matrix_sync(a, Zs + k0 * LD128 + rw, LD128);
#pragma unroll
        for (int j = 0; j < 4; j++) {
            wmma::fragment<wmma::matrix_b, 16, 16, 8, wmma::precision::tf32,
                           wmma::row_major> bf;
            wmma::load_matrix_sync(bf, Zs + k0 * LD128 + jt + j * 16, LD128);
            wmma::mma_sync(c[j], a, bf, c[j]);
        }
    }
#pragma unroll
    for (int j = 0; j < 4; j++)
        wmma::store_matrix_sync(Cs + rw * LD128 + jt + j * 16, c[j], LD128,
                                wmma::mem_row_major);
    __syncthreads();

    gds();

    float* Gb = &g_G[0][b][0][0];
#pragma unroll
    for (int q = 0; q < 8; q++) {
        int f = tid + q * 512;
        int row = f >> 5, c4 = (f & 31) * 4;
        float4 v = *(const float4*)&Cs[row * LD128 + c4];
        red_add_v4(&Gb[row * DP1 + c4], v);
    }
}

// ---------------------------------------------------------------------------
// Fused TR (tf32 wmma, ZERO operand staging). Block (b, h, s): cols [s*32,+32).
//   Phase 1: Ts = G @ P[:,slice]   (A direct from global fp32 G, B from g_PB)
//   Phase 2: Cs = Q @ Ts           (A direct from g_QT)
//   R[p][b][:,slice] += Cs/N       (vector reductions)
// 256 thr = 8 warps; warp w: rows w*16, cols {0,16}. Static smem 36KB.
// ---------------------------------------------------------------------------
__global__ __launch_bounds__(256)
void tr_kernel(int layer, int p) {
    __shared__ __align__(16) float Ts[DP1 * LD32];
    __shared__ __align__(16) float Cs[DP1 * LD32];

    const int b = blockIdx.x, h = blockIdx.y, s = blockIdx.z;
    const int c0 = s * 32;
    const int tid = threadIdx.x;
    const int w = tid >> 5;
    const int rw = w * 16;

    const float* Gb = &g_G[p][b][0][0];
    const float* PB = &g_PB[layer][h][0][0];
    const float* QT = &g_QT[layer][h][0][0];

    gds();   // G / R-zero from previous stage

    // Phase 1: Ts = G @ P[:, c0..c0+32)  — all operands straight from global
    wmma::fragment<wmma::accumulator, 16, 16, 8, float> c0f, c1f;
    wmma::fill_fragment(c0f, 0.0f);
    wmma::fill_fragment(c1f, 0.0f);
#pragma unroll
    for (int k0 = 0; k0 < DP1; k0 += 8) {
        wmma::fragment<wmma::matrix_a, 16, 16, 8, wmma::precision::tf32,
                       wmma::row_major> a;
        wmma::load_matrix_sync(a, Gb + rw * DP1 + k0, DP1);
        wmma::fragment<wmma::matrix_b, 16, 16, 8, wmma::precision::tf32,
                       wmma::row_major> b0, b1;
        wmma::load_matrix_sync(b0, PB + k0 * DP1 + c0, DP1);
        wmma::load_matrix_sync(b1, PB + k0 * DP1 + c0 + 16, DP1);
        wmma::mma_sync(c0f, a, b0, c0f);
        wmma::mma_sync(c1f, a, b1, c1f);
    }
#pragma unroll
    for (int t = 0; t < c0f.num_elements; t++) {
        c0f.x[t] = wmma::__float_to_tf32(c0f.x[t]);
        c1f.x[t] = wmma::__float_to_tf32(c1f.x[t]);
    }
    wmma::store_matrix_sync(Ts + rw * LD32, c0f, LD32, wmma::mem_row_major);
    wmma::store_matrix_sync(Ts + rw * LD32 + 16, c1f, LD32, wmma::mem_row_major);
    __syncthreads();

    // Phase 2: Cs = Q @ Ts  (A col_major straight from global QT)
    wmma::fill_fragment(c0f, 0.0f);
    wmma::fill_fragment(c1f, 0.0f);
#pragma unroll
    for (int k0 = 0; k0 < DP1; k0 += 8) {
        wmma::fragment<wmma::matrix_a, 16, 16, 8, wmma::precision::tf32,
                       wmma::col_major> a;
        wmma::load_matrix_sync(a, QT + k0 * DP1 + rw, DP1);
        wmma::fragment<wmma::matrix_b, 16, 16, 8, wmma::precision::tf32,
                       wmma::row_major> b0, b1;
        wmma::load_matrix_sync(b0, Ts + k0 * LD32, LD32);
        wmma::load_matrix_sync(b1, Ts + k0 * LD32 + 16, LD32);
        wmma::mma_sync(c0f, a, b0, c0f);
        wmma::mma_sync(c1f, a, b1, c1f);
    }
    wmma::store_matrix_sync(Cs + rw * LD32, c0f, LD32, wmma::mem_row_major);
    wmma::store_matrix_sync(Cs + rw * LD32 + 16, c1f, LD32, wmma::mem_row_major);
    __syncthreads();

    const float invN = 1.0f / (float)NTOK;
    float* Rb = &g_R[p][b][0][0];
#pragma unroll
    for (int q = 0; q < 4; q++) {
        int f = tid + q * 256;              // 0..1023 f4 (128x32)
        int row = f >> 3, c4 = (f & 7) * 4;
        float4 v = *(const float4*)&Cs[row * LD32 + c4];
        v.x *= invN; v.y *= invN; v.z *= invN; v.w *= invN;
        red_add_v4(&Rb[row * DP1 + c0 + c4], v);
    }
}

// ---------------------------------------------------------------------------
// update (merged c1+c2, tf32 wmma, ZERO operand staging):
//  d<4 (non-last): G col block c0=d*32:
//     H = G @ R[:,c0]  (A,B direct global); U = G[:,c0]fp32 + H;
//     S = R^T @ U      (A direct global, B smem); G' = U + S
//  d>=4 (or last d<4): W col block: S = R^T @ W[:,c0] (both direct global);
//     W' = W fp32 + S
// grid (8, last?4:8), 512 thr (16 warps: rows (w&7)*16, col (w>>3)*16).
// Static smem 36KB. Also zeroes g_R[p^1] (non-last).
// ---------------------------------------------------------------------------
__global__ __launch_bounds__(512)
void update_kernel(int p, int last) {
    __shared__ __align__(16) float Us[DP1 * LD32];
    __shared__ __align__(16) float Ss[DP1 * LD32];

    const int b = blockIdx.x, d = blockIdx.y;
    const int tid = threadIdx.x;
    const int w = tid >> 5;
    const int rw = (w & 7) * 16, jc = (w >> 3) * 16;

    const bool isW = last ? true : (d >= 4);
    const int c0 = (last ? d : (isW ? d - 4 : d)) * 32;

    const float* Rg = &g_R[p][b][0][0];
    const float* Gg = &g_G[p][b][0][0];
    const float* Wg = &g_W[p][b][0][0];

    gds();   // R from tr

    wmma::fragment<wmma::accumulator, 16, 16, 8, float> acc;

    if (!isW) {
        // GEMM1: H = G @ R[:,c0]  (direct global operands)
        wmma::fill_fragment(acc, 0.0f);
#pragma unroll
        for (int k0 = 0; k0 < DP1; k0 += 8) {
            wmma::fragment<wmma::matrix_a, 16, 16, 8, wmma::precision::tf32,
                           wmma::row_major> a;
            wmma::load_matrix_sync(a, Gg + rw * DP1 + k0, DP1);
            wmma::fragment<wmma::matrix_b, 16, 16, 8, wmma::precision::tf32,
                           wmma::row_major> bf;
            wmma::load_matrix_sync(bf, Rg + k0 * DP1 + c0 + jc, DP1);
            wmma::mma_sync(acc, a, bf, acc);
        }
        wmma::store_matrix_sync(Us + rw * LD32 + jc, acc, LD32,
                                wmma::mem_row_major);
        __syncthreads();

        // U = G fp32 + H
#pragma unroll
        for (int q = 0; q < 2; q++) {
            int f = tid + q * 512;          // 0..1023 f4 (128x32)
            int row = f >> 3, c4 = (f & 7) * 4;
            float4 hh = *(const float4*)&Us[row * LD32 + c4];
            float4 g = *(const float4*)&Gg[row * DP1 + c0 + c4];
            *(float4*)&Us[row * LD32 + c4] =
                make_float4(g.x + hh.x, g.y + hh.y, g.z + hh.z, g.w + hh.w);
        }
        __syncthreads();
    }

    // GEMM2: S = R^T @ (U | W[:,c0])
    wmma::fill_fragment(acc, 0.0f);
#pragma unroll
    for (int k0 = 0; k0 < DP1; k0 += 8) {
        wmma::fragment<wmma::matrix_a, 16, 16, 8, wmma::precision::tf32,
                       wmma::col_major> a;
        wmma::load_matrix_sync(a, Rg + k0 * DP1 + rw, DP1);
        wmma::fragment<wmma::matrix_b, 16, 16, 8, wmma::precision::tf32,
                       wmma::row_major> bf;
        if (isW)
            wmma::load_matrix_sync(bf, Wg + k0 * DP1 + c0 + jc, DP1);
        else
            wmma::load_matrix_sync(bf, Us + k0 * LD32 + jc, LD32);
        wmma::mma_sync(acc, a, bf, acc);
    }
    wmma::store_matrix_sync(Ss + rw * LD32 + jc, acc, LD32, wmma::mem_row_major);
    __syncthreads();

    if (!isW) {
        float* Gn = &g_G[p ^ 1][b][0][0];
#pragma unroll
        for (int q = 0; q < 2; q++) {
            int f = tid + q * 512;
            int row = f >> 3, c4 = (f & 7) * 4;
            float4 s = *(const float4*)&Ss[row * LD32 + c4];
            float4 u = *(const float4*)&Us[row * LD32 + c4];
            *(float4*)&Gn[row * DP1 + c0 + c4] =
                make_float4(u.x + s.x, u.y + s.y, u.z + s.z, u.w + s.w);
        }
    } else {
        float* Wn = &g_W[p ^ 1][b][0][0];
#pragma unroll
        for (int q = 0; q < 2; q++) {
            int f = tid + q * 512;
            int row = f >> 3, c4 = (f & 7) * 4;
            float4 s = *(const float4*)&Ss[row * LD32 + c4];
            float4 wb = *(const float4*)&Wg[row * DP1 + c0 + c4];
            *(float4*)&Wn[row * DP1 + c0 + c4] =
                make_float4(wb.x + s.x, wb.y + s.y, wb.z + s.z, wb.w + s.w);
        }
    }

    // zero next-parity R (non-last)
    if (!last) {
        float* Rn = &g_R[p ^ 1][0][0][0];
        int f = (b * 8 + d) * 512 + tid;     // 0..32767 f4
        *(float4*)&Rn[f * 4] = make_float4(0.f, 0.f, 0.f, 0.f);
    }
}

// ---------------------------------------------------------------------------
// Final (tf32 wmma on correction): Zout = Zin + Zin @ E^T, E = W[pw] - I.
// grid (8,8), 512 thr. Z staging (input-only) runs BEFORE the PDL sync.
// ---------------------------------------------------------------------------
__global__ __launch_bounds__(512)
void final_kernel(const float* __restrict__ Zin, float* __restrict__ Zout,
                  int pw) {
    extern __shared__ __align__(16) float dsm[];
    float* Zs = dsm;                 // [128][132]
    float* Es = dsm + DP1 * LD128;   // [128][132]

    const int b = blockIdx.x, rt = blockIdx.y;
    const int n0 = rt * 128;
    const int tid = threadIdx.x;
    const int w = tid >> 5;
    const int rw = (w & 7) * 16;
    const int jt = (w >> 3) * 64;

    const float* Zb = Zin + (size_t)b * NP1 * DP1;
    float* Zo = Zout + (size_t)b * NP1 * DP1;
    const float* Wb = &g_W[pw][b][0][0];

    // independent: stage Z (tf32)
#pragma unroll
    for (int q = 0; q < 8; q++) {
        int f = tid + q * 512;
        int row = f >> 5, c4 = (f & 31) * 4;
        *(float4*)&Zs[row * LD128 + c4] =
            tf32x4(*(const float4*)&Zb[(size_t)(n0 + row) * DP1 + c4]);
    }

    gds();   // W from last update

    // dependent: stage E = W - I (tf32)
#pragma unroll
    for (int q = 0; q < 8; q++) {
        int f = tid + q * 512;
        int row = f >> 5, c4 = (f & 31) * 4;
        float4 e = *(const float4*)&Wb[row * DP1 + c4];
        if (row >= c4 && row < c4 + 4) {
            if (row == c4)          e.x -= 1.0f;
            else if (row == c4 + 1) e.y -= 1.0f;
            else if (row == c4 + 2) e.z -= 1.0f;
            else                    e.w -= 1.0f;
        }
        *(float4*)&Es[row * LD128 + c4] = tf32x4(e);
    }
    __syncthreads();

    wmma::fragment<wmma::accumulator, 16, 16, 8, float> c[4];
#pragma unroll
    for (int j = 0; j < 4; j++) wmma::fill_fragment(c[j], 0.0f);

#pragma unroll
    for (int k0 = 0; k0 < DP1; k0 += 8) {
        wmma::fragment<wmma::matrix_a, 16, 16, 8, wmma::precision::tf32,
                       wmma::row_major> a;
        wmma::load_matrix_sync(a, Zs + rw * LD128 + k0, LD128);
#pragma unroll
        for (int j = 0; j < 4; j++) {
            wmma::fragment<wmma::matrix_b, 16, 16, 8, wmma::precision::tf32,
                           wmma::col_major> bf;
            wmma::load_matrix_sync(bf, Es + (jt + j * 16) * LD128 + k0, LD128);
            wmma::mma_sync(c[j], a, bf, c[j]);
        }
    }
    __syncthreads();
#pragma unroll
    for (int j = 0; j < 4; j++)
        wmma::store_matrix_sync(Zs + rw * LD128 + jt + j * 16, c[j], LD128,
                                wmma::mem_row_major);
    __syncthreads();

#pragma unroll
    for (int q = 0; q < 8; q++) {
        int f = tid + q * 512;
        int row = f >> 5, c4 = (f & 31) * 4;
        size_t off = (size_t)(n0 + row) * DP1 + c4;
        float4 z = *(const float4*)&Zb[off];
        float4 cc = *(const float4*)&Zs[row * LD128 + c4];
        *(float4*)&Zo[off] =
            make_float4(z.x + cc.x, z.y + cc.y, z.z + cc.z, z.w + cc.w);
    }
}

// ---------------------------------------------------------------------------
template <typename Kern, typename... Args>
static inline void pdl_launch(Kern kern, dim3 grid, dim3 block, size_t smem,
                              Args... args) {
    cudaLaunchConfig_t cfg = {};
    cfg.gridDim = grid;
    cfg.blockDim = block;
    cfg.dynamicSmemBytes = smem;
    cfg.stream = 0;
    cudaLaunchAttribute at[1];
    at[0].id = cudaLaunchAttributeProgrammaticStreamSerialization;
    at[0].val.programmaticStreamSerializationAllowed = 1;
    cfg.attrs = at;
    cfg.numAttrs = 1;
    cudaLaunchKernelEx(&cfg, kern, args...);
}

extern "C" void kernel_launch(void* const* d_in, const int* in_sizes, int n_in,
                              void* d_out, int out_size) {
    const float* Z_in     = (const float*)d_in[0];
    const float* allparam = (const float*)d_in[1];
    float* Z_out = (float*)d_out;

    cudaFuncSetAttribute(gram_kernel,
                         cudaFuncAttributeMaxDynamicSharedMemorySize, GRAM_SMEM);
    cudaFuncSetAttribute(final_kernel,
                         cudaFuncAttributeMaxDynamicSharedMemorySize, FIN_SMEM);

    pdl_launch(padinit_kernel, dim3(2048), dim3(256), 0, allparam);
    pdl_launch(gram_kernel, dim3(BATCH, 16), dim3(512), (size_t)GRAM_SMEM, Z_in);

    for (int l = 0; l < NLAYER; l++) {
        int p = l & 1;
        int last = (l == NLAYER - 1) ? 1 : 0;
        pdl_launch(tr_kernel, dim3(BATCH, NHEAD, 4), dim3(256), 0, l, p);
        pdl_launch(update_kernel, dim3(BATCH, last ? 4 : 8), dim3(512), 0,
                   p, last);
    }

    pdl_launch(final_kernel, dim3(BATCH, 8), dim3(512), (size_t)FIN_SMEM,
               Z_in, Z_out, NLAYER & 1);
}

// round 16
// speedup vs baseline: 1.8775x; 1.8775x over previous
#include <cuda_runtime.h>
#include <mma.h>
using namespace nvcuda;

#define BATCH   8
#define NP1     1024
#define DP1     128
#define NLAYER  4
#define NHEAD   8
#define NTOK    1023
#define DSMALL  127

#define LD128   132     // padded ld for 128-col tf32 operand
#define LD32    36      // padded ld for 32-col operand

// tr: Gs[128][132] + Ts[128][36]  -> 86016 B -> 2 blocks/SM
#define TR_SMEM   ((DP1 * LD128 + DP1 * LD32) * 4)
// update: Gs[128][132] + Rs[128][132] + Us[128][36]
#define UPD_SMEM  ((2 * DP1 * LD128 + DP1 * LD32) * 4)          // 153600
// gram: Zs[64][132] + Cs[128][132]
#define GRAM_SMEM ((64 * LD128 + DP1 * LD128) * 4)              // 101376
// final: Zs[128][132] + Es[128][132]
#define FIN_SMEM  ((2 * DP1 * LD128) * 4)                       // 135168

// ---------------------------------------------------------------------------
// g_PB[l][h][a][b] = Pfull[b][a]   (P^T, padded, PRE-ROUNDED tf32)
// g_QT[l][h][k][i] = Qfull[i][k]   (Q^T, padded, PRE-ROUNDED tf32)
// g_G[gp][b] : Gram ping-pong (layer l reads gp=l&1; update writes gp^1)
// g_R[p][b]  : R ping-pong (R[p^1] zeroed by update; R[0] by padinit)
// g_W[p][b]  : W = M^T ping-pong (I included, fp32 base)
// ---------------------------------------------------------------------------
__device__ __align__(16) float g_PB[NLAYER][NHEAD][DP1][DP1];
__device__ __align__(16) float g_QT[NLAYER][NHEAD][DP1][DP1];
__device__ __align__(16) float g_G [2][BATCH][DP1][DP1];
__device__ __align__(16) float g_R [2][BATCH][DP1][DP1];
__device__ __align__(16) float g_W [2][BATCH][DP1][DP1];

__device__ __forceinline__ float4 tf32x4(float4 v) {
    v.x = wmma::__float_to_tf32(v.x);  v.y = wmma::__float_to_tf32(v.y);
    v.z = wmma::__float_to_tf32(v.z);  v.w = wmma::__float_to_tf32(v.w);
    return v;
}

__device__ __forceinline__ void red_add_v4(float* ptr, float4 v) {
    asm volatile("red.global.add.v4.f32 [%0], {%1, %2, %3, %4};"
                 :: "l"(ptr), "f"(v.x), "f"(v.y), "f"(v.z), "f"(v.w)
                 : "memory");
}

// PDL: wait for the producer kernel before touching its output.
__device__ __forceinline__ void gds() {
#if __CUDA_ARCH__ >= 900
    cudaGridDependencySynchronize();
#endif
}

// ---------------------------------------------------------------------------
__global__ void padinit_kernel(const float* __restrict__ allparam) {
    int idx = blockIdx.x * blockDim.x + threadIdx.x;   // < 524288
    {
        int bb = idx & 127;
        int a  = (idx >> 7) & 127;
        int h  = (idx >> 14) & 7;
        int l  = idx >> 17;
        float pv = 0.0f, qv = 0.0f;
        if (bb < DSMALL && a < DSMALL) {
            const float* base = allparam
                + ((((size_t)l * NHEAD + h) * 2 + 0) * DSMALL + bb) * DSMALL + a;
            pv = base[0];
            qv = base[DSMALL * DSMALL];
        }
        if (bb == DSMALL && a == DSMALL) pv = 1.0f;
        g_PB[l][h][a][bb] = wmma::__float_to_tf32(pv);
        g_QT[l][h][a][bb] = wmma::__float_to_tf32(qv);
    }
    if (idx < BATCH * DP1 * DP1) {
        int j = idx & 127, i = (idx >> 7) & 127, b = idx >> 14;
        g_G[0][b][i][j] = 0.0f;
        g_R[0][b][i][j] = 0.0f;
        g_W[0][b][i][j] = (i == j) ? 1.0f : 0.0f;
    }
}

// ---------------------------------------------------------------------------
// Gram (tf32 wmma): G[0][b] += Zslab^T Zslab. grid (8,16), 512 thr.
// Staging + MMA independent of padinit; gds() guards only the reductions.
// ---------------------------------------------------------------------------
__global__ __launch_bounds__(512)
void gram_kernel(const float* __restrict__ Z) {
    extern __shared__ __align__(16) float dsm[];
    float* Zs = dsm;                 // [64][132]
    float* Cs = dsm + 64 * LD128;    // [128][132]

    const int b = blockIdx.x, s = blockIdx.y;
    const int tid = threadIdx.x;
    const int w = tid >> 5;
    const int rw = (w & 7) * 16;
    const int jt = (w >> 3) * 64;

    const float* Zb = Z + (size_t)b * NP1 * DP1;
    const int m0 = s * 64;

#pragma unroll
    for (int q = 0; q < 4; q++) {
        int f = tid + q * 512;
        int row = f >> 5, c4 = (f & 31) * 4;
        float4 v = make_float4(0.f, 0.f, 0.f, 0.f);
        if (m0 + row < NTOK)
            v = tf32x4(*(const float4*)&Zb[(size_t)(m0 + row) * DP1 + c4]);
        *(float4*)&Zs[row * LD128 + c4] = v;
    }
    __syncthreads();

    wmma::fragment<wmma::accumulator, 16, 16, 8, float> c[4];
#pragma unroll
    for (int j = 0; j < 4; j++) wmma::fill_fragment(c[j], 0.0f);

#pragma unroll
    for (int k0 = 0; k0 < 64; k0 += 8) {
        wmma::fragment<wmma::matrix_a, 16, 16, 8, wmma::precision::tf32,
                       wmma::col_major> a;
        wmma::load_matrix_sync(a, Zs + k0 * LD128 + rw, LD128);
#pragma unroll
        for (int j = 0; j < 4; j++) {
            wmma::fragment<wmma::matrix_b, 16, 16, 8, wmma::precision::tf32,
                           wmma::row_major> bf;
            wmma::load_matrix_sync(bf, Zs + k0 * LD128 + jt + j * 16, LD128);
            wmma::mma_sync(c[j], a, bf, c[j]);
        }
    }
#pragma unroll
    for (int j = 0; j < 4; j++)
        wmma::store_matrix_sync(Cs + rw * LD128 + jt + j * 16, c[j], LD128,
                                wmma::mem_row_major);
    __syncthreads();

    gds();   // wait for padinit's G zeroing only now

    float* Gb = &g_G[0][b][0][0];
#pragma unroll
    for (int q = 0; q < 8; q++) {
        int f = tid + q * 512;
        int row = f >> 5, c4 = (f & 31) * 4;
        float4 v = *(const float4*)&Cs[row * LD128 + c4];
        red_add_v4(&Gb[row * DP1 + c4], v);
    }
}

// ---------------------------------------------------------------------------
// Fused TR (tf32 wmma). Block (b, h, s): cols [s*32,+32). 256 thr = 8 warps.
// smem 86KB -> 2 blocks/SM; grid 256 -> real overlap.
// ---------------------------------------------------------------------------
__global__ __launch_bounds__(256, 2)
void tr_kernel(int layer, int p) {
    extern __shared__ __align__(16) float dsm[];
    float* Gs = dsm;                  // [128][132]
    float* Ts = dsm + DP1 * LD128;    // [128][36]

    const int b = blockIdx.x, h = blockIdx.y, s = blockIdx.z;
    const int c0 = s * 32;
    const int tid = threadIdx.x;
    const int w = tid >> 5;
    const int rw = w * 16;

    const float* Gb = &g_G[p][b][0][0];
    const float* PB = &g_PB[layer][h][0][0];
    const float* QT = &g_QT[layer][h][0][0];

    gds();   // G / R-zero from previous stage

    // stage G (tf32 round)
#pragma unroll
    for (int q = 0; q < 16; q++) {
        int f = tid + q * 256;
        int row = f >> 5, c4 = (f & 31) * 4;
        *(float4*)&Gs[row * LD128 + c4] =
            tf32x4(*(const float4*)&Gb[row * DP1 + c4]);
    }
    __syncthreads();

    // Phase 1: Ts = G @ P[:, c0..c0+32)
    wmma::fragment<wmma::accumulator, 16, 16, 8, float> c0f, c1f;
    wmma::fill_fragment(c0f, 0.0f);
    wmma::fill_fragment(c1f, 0.0f);
#pragma unroll
    for (int k0 = 0; k0 < DP1; k0 += 8) {
        wmma::fragment<wmma::matrix_a, 16, 16, 8, wmma::precision::tf32,
                       wmma::row_major> a;
        wmma::load_matrix_sync(a, Gs + rw * LD128 + k0, LD128);
        wmma::fragment<wmma::matrix_b, 16, 16, 8, wmma::precision::tf32,
                       wmma::row_major> b0, b1;
        wmma::load_matrix_sync(b0, PB + k0 * DP1 + c0, DP1);
        wmma::load_matrix_sync(b1, PB + k0 * DP1 + c0 + 16, DP1);
        wmma::mma_sync(c0f, a, b0, c0f);
        wmma::mma_sync(c1f, a, b1, c1f);
    }
#pragma unroll
    for (int t = 0; t < c0f.num_elements; t++) {
        c0f.x[t] = wmma::__float_to_tf32(c0f.x[t]);
        c1f.x[t] = wmma::__float_to_tf32(c1f.x[t]);
    }
    wmma::store_matrix_sync(Ts + rw * LD32, c0f, LD32, wmma::mem_row_major);
    wmma::store_matrix_sync(Ts + rw * LD32 + 16, c1f, LD32, wmma::mem_row_major);
    __syncthreads();

    // Phase 2: C = Q @ Ts  (A col_major straight from global QT)
    wmma::fill_fragment(c0f, 0.0f);
    wmma::fill_fragment(c1f, 0.0f);
#pragma unroll
    for (int k0 = 0; k0 < DP1; k0 += 8) {
        wmma::fragment<wmma::matrix_a, 16, 16, 8, wmma::precision::tf32,
                       wmma::col_major> a;
        wmma::load_matrix_sync(a, QT + k0 * DP1 + rw, DP1);
        wmma::fragment<wmma::matrix_b, 16, 16, 8, wmma::precision::tf32,
                       wmma::row_major> b0, b1;
        wmma::load_matrix_sync(b0, Ts + k0 * LD32, LD32);
        wmma::load_matrix_sync(b1, Ts + k0 * LD32 + 16, LD32);
        wmma::mma_sync(c0f, a, b0, c0f);
        wmma::mma_sync(c1f, a, b1, c1f);
    }
    __syncthreads();   // Ts reads done; reuse Ts for C
    wmma::store_matrix_sync(Ts + rw * LD32, c0f, LD32, wmma::mem_row_major);
    wmma::store_matrix_sync(Ts + rw * LD32 + 16, c1f, LD32, wmma::mem_row_major);
    __syncthreads();

    const float invN = 1.0f / (float)NTOK;
    float* Rb = &g_R[p][b][0][0];
#pragma unroll
    for (int q = 0; q < 4; q++) {
        int f = tid + q * 256;              // 0..1023 f4 (128x32)
        int row = f >> 3, c4 = (f & 7) * 4;
        float4 v = *(const float4*)&Ts[row * LD32 + c4];
        v.x *= invN; v.y *= invN; v.z *= invN; v.w *= invN;
        red_add_v4(&Rb[row * DP1 + c0 + c4], v);
    }
}

// ---------------------------------------------------------------------------
// update (merged c1+c2, tf32 wmma, column-block):
//  d<4 (non-last): G col block; d>=4 (or last): W col block.
// grid (8, last?4:8), 512 thr. Also zeroes g_R[p^1] (non-last).
// PDL hoist: G/W staging (written by the PREVIOUS update/gram — transitively
// complete) runs BEFORE gds(); only the R staging waits on tr.
// ---------------------------------------------------------------------------
__global__ __launch_bounds__(512)
void update_kernel(int p, int last) {
    extern __shared__ __align__(16) float dsm[];
    float* Gs = dsm;                      // [128][132] (G stage; later S buffer)
    float* Rs = dsm + DP1 * LD128;        // [128][132]
    float* Us = dsm + 2 * DP1 * LD128;    // [128][36]  (U or Wc)

    const int b = blockIdx.x, d = blockIdx.y;
    const int tid = threadIdx.x;
    const int w = tid >> 5;
    const int rw = (w & 7) * 16, jc = (w >> 3) * 16;

    const bool isW = last ? true : (d >= 4);
    const int c0 = (last ? d : (isW ? d - 4 : d)) * 32;

    const float* Rg = &g_R[p][b][0][0];
    const float* Gg = &g_G[p][b][0][0];
    const float* Wg = &g_W[p][b][0][0];

    // ---- PDL-independent staging: G (G blocks) / Wc (W blocks) ----
    if (!isW) {
#pragma unroll
        for (int q = 0; q < 8; q++) {
            int f = tid + q * 512;
            int row = f >> 5, c4 = (f & 31) * 4;
            *(float4*)&Gs[row * LD128 + c4] =
                tf32x4(*(const float4*)&Gg[row * DP1 + c4]);
        }
    } else {
#pragma unroll
        for (int q = 0; q < 2; q++) {
            int f = tid + q * 512;          // 0..1023 f4 (128x32)
            int row = f >> 3, c4 = (f & 7) * 4;
            *(float4*)&Us[row * LD32 + c4] =
                tf32x4(*(const float4*)&Wg[row * DP1 + c0 + c4]);
        }
    }

    gds();   // R from tr — only now

    // ---- dependent staging: R ----
#pragma unroll
    for (int q = 0; q < 8; q++) {
        int f = tid + q * 512;
        int row = f >> 5, c4 = (f & 31) * 4;
        *(float4*)&Rs[row * LD128 + c4] =
            tf32x4(*(const float4*)&Rg[row * DP1 + c4]);
    }
    __syncthreads();

    wmma::fragment<wmma::accumulator, 16, 16, 8, float> acc;

    if (!isW) {
        // GEMM1: H = G @ R[:,c0]
        wmma::fill_fragment(acc, 0.0f);
#pragma unroll
        for (int k0 = 0; k0 < DP1; k0 += 8) {
            wmma::fragment<wmma::matrix_a, 16, 16, 8, wmma::precision::tf32,
                           wmma::row_major> a;
            wmma::load_matrix_sync(a, Gs + rw * LD128 + k0, LD128);
            wmma::fragment<wmma::matrix_b, 16, 16, 8, wmma::precision::tf32,
                           wmma::row_major> bf;
            wmma::load_matrix_sync(bf, Rs + k0 * LD128 + c0 + jc, LD128);
            wmma::mma_sync(acc, a, bf, acc);
        }
        wmma::store_matrix_sync(Us + rw * LD32 + jc, acc, LD32,
                                wmma::mem_row_major);
        __syncthreads();

        // U = G_glob fp32 + H
#pragma unroll
        for (int q = 0; q < 2; q++) {
            int f = tid + q * 512;
            int row = f >> 3, c4 = (f & 7) * 4;
            float4 h = *(const float4*)&Us[row * LD32 + c4];
            float4 g = *(const float4*)&Gg[row * DP1 + c0 + c4];
            *(float4*)&Us[row * LD32 + c4] =
                make_float4(g.x + h.x, g.y + h.y, g.z + h.z, g.w + h.w);
        }
        __syncthreads();
    }

    // GEMM2 / W-GEMM: S = R^T @ Us
    wmma::fill_fragment(acc, 0.0f);
#pragma unroll
    for (int k0 = 0; k0 < DP1; k0 += 8) {
        wmma::fragment<wmma::matrix_a, 16, 16, 8, wmma::precision::tf32,
                       wmma::col_major> a;
        wmma::load_matrix_sync(a, Rs + k0 * LD128 + rw, LD128);
        wmma::fragment<wmma::matrix_b, 16, 16, 8, wmma::precision::tf32,
                       wmma::row_major> bf;
        wmma::load_matrix_sync(bf, Us + k0 * LD32 + jc, LD32);
        wmma::mma_sync(acc, a, bf, acc);
    }
    __syncthreads();   // Gs dead (G blocks) / scratch (W blocks): S buffer
    wmma::store_matrix_sync(Gs + rw * LD32 + jc, acc, LD32, wmma::mem_row_major);
    __syncthreads();

    if (!isW) {
        float* Gn = &g_G[p ^ 1][b][0][0];
#pragma unroll
        for (int q = 0; q < 2; q++) {
            int f = tid + q * 512;
            int row = f >> 3, c4 = (f & 7) * 4;
            float4 s = *(const float4*)&Gs[row * LD32 + c4];
            float4 u = *(const float4*)&Us[row * LD32 + c4];
            *(float4*)&Gn[row * DP1 + c0 + c4] =
                make_float4(u.x + s.x, u.y + s.y, u.z + s.z, u.w + s.w);
        }
    } else {
        float* Wn = &g_W[p ^ 1][b][0][0];
#pragma unroll
        for (int q = 0; q < 2; q++) {
            int f = tid + q * 512;
            int row = f >> 3, c4 = (f & 7) * 4;
            float4 s = *(const float4*)&Gs[row * LD32 + c4];
            float4 wb = *(const float4*)&Wg[row * DP1 + c0 + c4];   // fp32 base
            *(float4*)&Wn[row * DP1 + c0 + c4] =
                make_float4(wb.x + s.x, wb.y + s.y, wb.z + s.z, wb.w + s.w);
        }
    }

    // zero next-parity R (non-last)
    if (!last) {
        float* Rn = &g_R[p ^ 1][0][0][0];
        int f = (b * 8 + d) * 512 + tid;     // 0..32767 f4
        *(float4*)&Rn[f * 4] = make_float4(0.f, 0.f, 0.f, 0.f);
    }
}

// ---------------------------------------------------------------------------
// Final (tf32 wmma on correction): Zout = Zin + Zin @ E^T, E = W[pw] - I.
// grid (8,8), 512 thr. Z staging (input-only) runs BEFORE the PDL sync.
// ---------------------------------------------------------------------------
__global__ __launch_bounds__(512)
void final_kernel(const float* __restrict__ Zin, float* __restrict__ Zout,
                  int pw) {
    extern __shared__ __align__(16) float dsm[];
    float* Zs = dsm;                 // [128][132]
    float* Es = dsm + DP1 * LD128;   // [128][132]

    const int b = blockIdx.x, rt = blockIdx.y;
    const int n0 = rt * 128;
    const int tid = threadIdx.x;
    const int w = tid >> 5;
    const int rw = (w & 7) * 16;
    const int jt = (w >> 3) * 64;

    const float* Zb = Zin + (size_t)b * NP1 * DP1;
    float* Zo = Zout + (size_t)b * NP1 * DP1;
    const float* Wb = &g_W[pw][b][0][0];

    // independent: stage Z (tf32)
#pragma unroll
    for (int q = 0; q < 8; q++) {
        int f = tid + q * 512;
        int row = f >> 5, c4 = (f & 31) * 4;
        *(float4*)&Zs[row * LD128 + c4] =
            tf32x4(*(const float4*)&Zb[(size_t)(n0 + row) * DP1 + c4]);
    }

    gds();   // W from last update

    // dependent: stage E = W - I (tf32)
#pragma unroll
    for (int q = 0; q < 8; q++) {
        int f = tid + q * 512;
        int row = f >> 5, c4 = (f & 31) * 4;
        float4 e = *(const float4*)&Wb[row * DP1 + c4];
        if (row >= c4 && row < c4 + 4) {
            if (row == c4)          e.x -= 1.0f;
            else if (row == c4 + 1) e.y -= 1.0f;
            else if (row == c4 + 2) e.z -= 1.0f;
            else                    e.w -= 1.0f;
        }
        *(float4*)&Es[row * LD128 + c4] = tf32x4(e);
    }
    __syncthreads();

    wmma::fragment<wmma::accumulator, 16, 16, 8, float> c[4];
#pragma unroll
    for (int j = 0; j < 4; j++) wmma::fill_fragment(c[j], 0.0f);

#pragma unroll
    for (int k0 = 0; k0 < DP1; k0 += 8) {
        wmma::fragment<wmma::matrix_a, 16, 16, 8, wmma::precision::tf32,
                       wmma::row_major> a;
        wmma::load_matrix_sync(a, Zs + rw * LD128 + k0, LD128);
#pragma unroll
        for (int j = 0; j < 4; j++) {
            wmma::fragment<wmma::matrix_b, 16, 16, 8, wmma::precision::tf32,
                           wmma::col_major> bf;
            wmma::load_matrix_sync(bf, Es + (jt + j * 16) * LD128 + k0, LD128);
            wmma::mma_sync(c[j], a, bf, c[j]);
        }
    }
    __syncthreads();
#pragma unroll
    for (int j = 0; j < 4; j++)
        wmma::store_matrix_sync(Zs + rw * LD128 + jt + j * 16, c[j], LD128,
                                wmma::mem_row_major);
    __syncthreads();

#pragma unroll
    for (int q = 0; q < 8; q++) {
        int f = tid + q * 512;
        int row = f >> 5, c4 = (f & 31) * 4;
        size_t off = (size_t)(n0 + row) * DP1 + c4;
        float4 z = *(const float4*)&Zb[off];
        float4 cc = *(const float4*)&Zs[row * LD128 + c4];
        *(float4*)&Zo[off] =
            make_float4(z.x + cc.x, z.y + cc.y, z.z + cc.z, z.w + cc.w);
    }
}

// ---------------------------------------------------------------------------
// PDL launch helper: programmatic stream serialization on every launch.
// ---------------------------------------------------------------------------
template <typename Kern, typename... Args>
static inline void pdl_launch(Kern kern, dim3 grid, dim3 block, size_t smem,
                              Args... args) {
    cudaLaunchConfig_t cfg = {};
    cfg.gridDim = grid;
    cfg.blockDim = block;
    cfg.dynamicSmemBytes = smem;
    cfg.stream = 0;
    cudaLaunchAttribute at[1];
    at[0].id = cudaLaunchAttributeProgrammaticStreamSerialization;
    at[0].val.programmaticStreamSerializationAllowed = 1;
    cfg.attrs = at;
    cfg.numAttrs = 1;
    cudaLaunchKernelEx(&cfg, kern, args...);
}

extern "C" void kernel_launch(void* const* d_in, const int* in_sizes, int n_in,
                              void* d_out, int out_size) {
    const float* Z_in     = (const float*)d_in[0];
    const float* allparam = (const float*)d_in[1];
    float* Z_out = (float*)d_out;

    cudaFuncSetAttribute(tr_kernel,
                         cudaFuncAttributeMaxDynamicSharedMemorySize, TR_SMEM);
    cudaFuncSetAttribute(update_kernel,
                         cudaFuncAttributeMaxDynamicSharedMemorySize, UPD_SMEM);
    cudaFuncSetAttribute(gram_kernel,
                         cudaFuncAttributeMaxDynamicSharedMemorySize, GRAM_SMEM);
    cudaFuncSetAttribute(final_kernel,
                         cudaFuncAttributeMaxDynamicSharedMemorySize, FIN_SMEM);

    pdl_launch(padinit_kernel, dim3(2048), dim3(256), 0, allparam);
    pdl_launch(gram_kernel, dim3(BATCH, 16), dim3(512), (size_t)GRAM_SMEM, Z_in);

    for (int l = 0; l < NLAYER; l++) {
        int p = l & 1;
        int last = (l == NLAYER - 1) ? 1 : 0;
        pdl_launch(tr_kernel, dim3(BATCH, NHEAD, 4), dim3(256),
                   (size_t)TR_SMEM, l, p);
        pdl_launch(update_kernel, dim3(BATCH, last ? 4 : 8), dim3(512),
                   (size_t)UPD_SMEM, p, last);
    }

    pdl_launch(final_kernel, dim3(BATCH, 8), dim3(512), (size_t)FIN_SMEM,
               Z_in, Z_out, NLAYER & 1);
}